// round 1
// baseline (speedup 1.0000x reference)
#include <cuda_runtime.h>
#include <math.h>

// Problem constants
#define BATCH   64
#define NSEQ    196
#define CDIM    1024
#define NHEAD   32
#define HDIM    32
#define MROWS   12544            // BATCH*NSEQ
#define QKVN    3072             // 3*CDIM

// Scratch (static device allocations — no cudaMalloc allowed)
__device__ float g_qkv[(size_t)MROWS * QKVN];   // [12544, 3072]
__device__ float g_att[(size_t)MROWS * CDIM];   // [12544, 1024]

// ---------------------------------------------------------------------------
// Tiled SGEMM: C[M,N] = A[M,K] * B[K,N] (+ bias[N]).  128x128 tile, BK=8,
// 256 threads, 8x8 microtile per thread (split 4+4 for conflict-free LDS.128).
// M % 128 == 0, N % 128 == 0, K % 8 == 0 guaranteed by the shapes here.
// ---------------------------------------------------------------------------
__global__ __launch_bounds__(256) void sgemm128(
    const float* __restrict__ A, const float* __restrict__ B,
    float* __restrict__ C, const float* __restrict__ bias,
    int M, int N, int K)
{
    __shared__ float As[8][128];
    __shared__ float Bs[8][128];

    const int tid = threadIdx.x;
    const int tx  = tid & 15;        // 0..15 -> column groups
    const int ty  = tid >> 4;        // 0..15 -> row groups
    const int bx  = blockIdx.x;
    const int by  = blockIdx.y;

    const float* Ab = A + (size_t)by * 128 * K;
    const float* Bb = B + (size_t)bx * 128;

    // global->shared load mapping
    const int arow = tid >> 1;          // 0..127
    const int acol = (tid & 1) * 4;     // 0 or 4
    const int brow = tid >> 5;          // 0..7
    const int bcol = (tid & 31) * 4;    // 0..124

    float acc[8][8];
    #pragma unroll
    for (int i = 0; i < 8; i++)
        #pragma unroll
        for (int j = 0; j < 8; j++) acc[i][j] = 0.0f;

    for (int k0 = 0; k0 < K; k0 += 8) {
        // issue global loads before the barrier (overlap with prior compute)
        const float4 av = *(const float4*)(Ab + (size_t)arow * K + k0 + acol);
        const float4 bv = *(const float4*)(Bb + (size_t)(k0 + brow) * N + bcol);

        __syncthreads();   // previous tile's compute must be done before overwrite
        As[acol + 0][arow] = av.x;
        As[acol + 1][arow] = av.y;
        As[acol + 2][arow] = av.z;
        As[acol + 3][arow] = av.w;
        *(float4*)(&Bs[brow][bcol]) = bv;
        __syncthreads();

        #pragma unroll
        for (int kk = 0; kk < 8; kk++) {
            float a[8], b[8];
            const float4 a0 = *(const float4*)(&As[kk][ty * 4]);
            const float4 a1 = *(const float4*)(&As[kk][64 + ty * 4]);
            const float4 b0 = *(const float4*)(&Bs[kk][tx * 4]);
            const float4 b1 = *(const float4*)(&Bs[kk][64 + tx * 4]);
            a[0]=a0.x; a[1]=a0.y; a[2]=a0.z; a[3]=a0.w;
            a[4]=a1.x; a[5]=a1.y; a[6]=a1.z; a[7]=a1.w;
            b[0]=b0.x; b[1]=b0.y; b[2]=b0.z; b[3]=b0.w;
            b[4]=b1.x; b[5]=b1.y; b[6]=b1.z; b[7]=b1.w;
            #pragma unroll
            for (int i = 0; i < 8; i++)
                #pragma unroll
                for (int j = 0; j < 8; j++)
                    acc[i][j] = fmaf(a[i], b[j], acc[i][j]);
        }
    }

    // epilogue: rows {ty*4+i, 64+ty*4+i}, cols {tx*4+j, 64+tx*4+j}
    #pragma unroll
    for (int ih = 0; ih < 2; ih++) {
        #pragma unroll
        for (int i = 0; i < 4; i++) {
            const int r = by * 128 + ih * 64 + ty * 4 + i;
            float* crow = C + (size_t)r * N + bx * 128;
            #pragma unroll
            for (int jh = 0; jh < 2; jh++) {
                const int c = jh * 64 + tx * 4;
                float4 v;
                v.x = acc[ih * 4 + i][jh * 4 + 0];
                v.y = acc[ih * 4 + i][jh * 4 + 1];
                v.z = acc[ih * 4 + i][jh * 4 + 2];
                v.w = acc[ih * 4 + i][jh * 4 + 3];
                if (bias) {
                    const float4 bb = *(const float4*)(bias + bx * 128 + c);
                    v.x += bb.x; v.y += bb.y; v.z += bb.z; v.w += bb.w;
                }
                *(float4*)(crow + c) = v;
            }
        }
    }
}

// ---------------------------------------------------------------------------
// Fused attention: one block per (b,h). Thread-per-query-row flash-style
// single pass (no max subtraction — logits bounded by ~|8|, safe in fp32).
// K/V tiles staged in dynamic smem; rpk column h staged in smem; relative
// position index recomputed arithmetically (deterministic closed form).
// ---------------------------------------------------------------------------
#define ATT_THREADS 224
#define ATT_SMEM    ((2 * NSEQ * HDIM + 729) * (int)sizeof(float))   // 53092 B

__global__ __launch_bounds__(ATT_THREADS) void attention_kernel(
    const float* __restrict__ qkv,   // [12544, 3072]
    const float* __restrict__ rpk,   // [729, 32]
    float* __restrict__ out)         // [12544, 1024]  (B,N,H,HD)
{
    extern __shared__ float smem[];
    float* Ksh = smem;                       // [196][32]
    float* Vsh = smem + NSEQ * HDIM;         // [196][32]
    float* rsh = smem + 2 * NSEQ * HDIM;     // [729]

    const int h   = blockIdx.x;
    const int b   = blockIdx.y;
    const int tid = threadIdx.x;

    const float* base = qkv + (size_t)b * NSEQ * QKVN + h * HDIM;

    // cooperative K/V stage (coalesced float4)
    for (int f = tid; f < NSEQ * 8; f += ATT_THREADS) {
        const int j  = f >> 3;
        const int d4 = (f & 7) * 4;
        const size_t row = (size_t)j * QKVN;
        *(float4*)(Ksh + j * HDIM + d4) = *(const float4*)(base + row + CDIM  + d4);
        *(float4*)(Vsh + j * HDIM + d4) = *(const float4*)(base + row + 2*CDIM + d4);
    }
    // rpk column h
    for (int i = tid; i < 729; i += ATT_THREADS)
        rsh[i] = rpk[(size_t)i * HDIM + h];
    __syncthreads();

    if (tid < NSEQ) {
        const int r = tid;
        const float scale = 0.17677669529663687f;  // HD^-0.5

        float q[HDIM];
        #pragma unroll
        for (int d4 = 0; d4 < 8; d4++) {
            const float4 qv = *(const float4*)(base + (size_t)r * QKVN + d4 * 4);
            q[d4*4+0] = qv.x * scale;
            q[d4*4+1] = qv.y * scale;
            q[d4*4+2] = qv.z * scale;
            q[d4*4+3] = qv.w * scale;
        }

        float acc[HDIM];
        #pragma unroll
        for (int d = 0; d < HDIM; d++) acc[d] = 0.0f;
        float denom = 0.0f;

        // idx = (yi - yj + 13)*27 + (xi - xj + 13) = dyc - (yj*27 + xj)
        const int dyc = (r / 14 + 13) * 27 + (r % 14) + 13;
        int t = 0, xj = 0;

        #pragma unroll 2
        for (int j = 0; j < NSEQ; j++) {
            const float* kj = Ksh + j * HDIM;
            float s0 = 0.f, s1 = 0.f, s2 = 0.f, s3 = 0.f;
            #pragma unroll
            for (int d4 = 0; d4 < 8; d4++) {
                const float4 kv = *(const float4*)(kj + d4 * 4);
                s0 = fmaf(q[d4*4+0], kv.x, s0);
                s1 = fmaf(q[d4*4+1], kv.y, s1);
                s2 = fmaf(q[d4*4+2], kv.z, s2);
                s3 = fmaf(q[d4*4+3], kv.w, s3);
            }
            const float logit = (s0 + s1) + (s2 + s3) + rsh[dyc - t];
            const float p = __expf(logit);
            denom += p;

            const float* vj = Vsh + j * HDIM;
            #pragma unroll
            for (int d4 = 0; d4 < 8; d4++) {
                const float4 vv = *(const float4*)(vj + d4 * 4);
                acc[d4*4+0] = fmaf(p, vv.x, acc[d4*4+0]);
                acc[d4*4+1] = fmaf(p, vv.y, acc[d4*4+1]);
                acc[d4*4+2] = fmaf(p, vv.z, acc[d4*4+2]);
                acc[d4*4+3] = fmaf(p, vv.w, acc[d4*4+3]);
            }

            // advance (yj, xj)
            t++;
            if (++xj == 14) { xj = 0; t += 13; }   // t = yj*27 + xj
        }

        const float inv = 1.0f / denom;
        float* o = out + (size_t)(b * NSEQ + r) * CDIM + h * HDIM;
        #pragma unroll
        for (int d4 = 0; d4 < 8; d4++) {
            float4 v;
            v.x = acc[d4*4+0] * inv;
            v.y = acc[d4*4+1] * inv;
            v.z = acc[d4*4+2] * inv;
            v.w = acc[d4*4+3] * inv;
            *(float4*)(o + d4 * 4) = v;
        }
    }
}

// ---------------------------------------------------------------------------
// Launch
// inputs: 0:x[64,196,1024] 1:W_qkv[1024,3072] 2:W_proj[1024,1024]
//         3:b_proj[1024] 4:rpk[729,32] 5:rel_idx[196,196] (recomputed, unused)
// output: float [64,196,1024]
// ---------------------------------------------------------------------------
extern "C" void kernel_launch(void* const* d_in, const int* in_sizes, int n_in,
                              void* d_out, int out_size)
{
    const float* x      = (const float*)d_in[0];
    const float* W_qkv  = (const float*)d_in[1];
    const float* W_proj = (const float*)d_in[2];
    const float* b_proj = (const float*)d_in[3];
    const float* rpk    = (const float*)d_in[4];
    float* out = (float*)d_out;

    float *qkv, *att;
    cudaGetSymbolAddress((void**)&qkv, g_qkv);
    cudaGetSymbolAddress((void**)&att, g_att);

    // 1) QKV projection: [12544,1024] x [1024,3072]
    {
        dim3 grid(QKVN / 128, MROWS / 128);
        sgemm128<<<grid, 256>>>(x, W_qkv, qkv, nullptr, MROWS, QKVN, CDIM);
    }

    // 2) fused attention per (b,h)
    {
        cudaFuncSetAttribute(attention_kernel,
                             cudaFuncAttributeMaxDynamicSharedMemorySize, ATT_SMEM);
        dim3 grid(NHEAD, BATCH);
        attention_kernel<<<grid, ATT_THREADS, ATT_SMEM>>>(qkv, rpk, att);
    }

    // 3) output projection: [12544,1024] x [1024,1024] + bias
    {
        dim3 grid(CDIM / 128, MROWS / 128);
        sgemm128<<<grid, 256>>>(att, W_proj, out, b_proj, MROWS, CDIM, CDIM);
    }
}

// round 4
// speedup vs baseline: 1.6872x; 1.6872x over previous
#include <cuda_runtime.h>
#include <cuda_bf16.h>
#include <mma.h>
#include <stdint.h>
#include <math.h>

using namespace nvcuda;

// Problem constants
#define BATCH   64
#define NSEQ    196
#define CDIM    1024
#define NHEAD   32
#define HDIM    32
#define MROWS   12544            // BATCH*NSEQ
#define QKVN    3072             // 3*CDIM

// ---------------------------------------------------------------------------
// Static scratch (no cudaMalloc allowed)
// ---------------------------------------------------------------------------
__device__ float g_qkv[(size_t)MROWS * QKVN];       // [12544, 3072] fp32
__device__ float g_att[(size_t)MROWS * CDIM];       // [12544, 1024] fp32
__device__ __nv_bfloat16 g_xh[(size_t)MROWS * CDIM];
__device__ __nv_bfloat16 g_xl[(size_t)MROWS * CDIM];
__device__ __nv_bfloat16 g_wqh[(size_t)QKVN * CDIM];   // W_qkv^T [3072,1024]
__device__ __nv_bfloat16 g_wql[(size_t)QKVN * CDIM];
__device__ __nv_bfloat16 g_wph[(size_t)CDIM * CDIM];   // W_proj^T [1024,1024]
__device__ __nv_bfloat16 g_wpl[(size_t)CDIM * CDIM];
__device__ __nv_bfloat16 g_ath[(size_t)MROWS * CDIM];
__device__ __nv_bfloat16 g_atl[(size_t)MROWS * CDIM];

// ---------------------------------------------------------------------------
// cp.async helper (baseline PTX, sm_80+)
// ---------------------------------------------------------------------------
__device__ __forceinline__ uint32_t smem_u32(const void* p) {
    uint32_t a;
    asm("{ .reg .u64 t; cvta.to.shared.u64 t, %1; cvt.u32.u64 %0, t; }"
        : "=r"(a) : "l"(p));
    return a;
}
__device__ __forceinline__ void cp16(uint32_t dst, const void* src) {
    asm volatile("cp.async.cg.shared.global [%0], [%1], 16;\n"
                 :: "r"(dst), "l"(src));
}

// ---------------------------------------------------------------------------
// bf16-split conversion kernels
// ---------------------------------------------------------------------------
__global__ __launch_bounds__(256) void split4_kernel(
    const float* __restrict__ in, __nv_bfloat16* __restrict__ hi,
    __nv_bfloat16* __restrict__ lo)
{
    const size_t i0 = ((size_t)blockIdx.x * 256 + threadIdx.x) * 4;
    const float4 v = *(const float4*)(in + i0);
    __nv_bfloat16 h0 = __float2bfloat16(v.x), h1 = __float2bfloat16(v.y);
    __nv_bfloat16 h2 = __float2bfloat16(v.z), h3 = __float2bfloat16(v.w);
    __nv_bfloat16 l0 = __float2bfloat16(v.x - __bfloat162float(h0));
    __nv_bfloat16 l1 = __float2bfloat16(v.y - __bfloat162float(h1));
    __nv_bfloat16 l2 = __float2bfloat16(v.z - __bfloat162float(h2));
    __nv_bfloat16 l3 = __float2bfloat16(v.w - __bfloat162float(h3));
    *(__nv_bfloat162*)(hi + i0)     = __nv_bfloat162(h0, h1);
    *(__nv_bfloat162*)(hi + i0 + 2) = __nv_bfloat162(h2, h3);
    *(__nv_bfloat162*)(lo + i0)     = __nv_bfloat162(l0, l1);
    *(__nv_bfloat162*)(lo + i0 + 2) = __nv_bfloat162(l2, l3);
}

// in: [K, N] fp32 row-major  ->  hi/lo: [N, K] bf16 row-major
__global__ __launch_bounds__(256) void transpose_split_kernel(
    const float* __restrict__ in, __nv_bfloat16* __restrict__ hi,
    __nv_bfloat16* __restrict__ lo, int K, int N)
{
    __shared__ float t[32][33];
    const int bx = blockIdx.x;   // tile over N
    const int by = blockIdx.y;   // tile over K
    const int x = bx * 32 + threadIdx.x;
    #pragma unroll
    for (int i = 0; i < 32; i += 8) {
        const int y = by * 32 + threadIdx.y + i;
        t[threadIdx.y + i][threadIdx.x] = in[(size_t)y * N + x];
    }
    __syncthreads();
    const int k = by * 32 + threadIdx.x;
    #pragma unroll
    for (int i = 0; i < 32; i += 8) {
        const int n = bx * 32 + threadIdx.y + i;
        const float v = t[threadIdx.x][threadIdx.y + i];
        const __nv_bfloat16 h = __float2bfloat16(v);
        hi[(size_t)n * K + k] = h;
        lo[(size_t)n * K + k] = __float2bfloat16(v - __bfloat162float(h));
    }
}

// ---------------------------------------------------------------------------
// HMMA bf16-split GEMM: C[M,N] = A*B^T (+bias).
// A=[M,K] hi/lo bf16 row-major, B=[N,K] hi/lo bf16 row-major.
// 128x128 tile, BK=32, 8 warps (4M x 2N), warp tile 32x64,
// wmma 16x16x16 bf16->fp32, cp.async double buffer, bias epilogue via smem.
// ---------------------------------------------------------------------------
#define BK       32
#define LDA      40                           // padded bf16 leading dim (80 B)
#define MAT_T    (128 * LDA * 2)              // 10240 B per matrix tile
#define STAGE_B  (4 * MAT_T)                  // 40960 B (Ah, Al, Bh, Bl)
#define GEMM_SMEM (2 * STAGE_B)               // 81920 B (>= epilogue 67584 B)
#define LDC      132                          // fp32 epilogue leading dim

__global__ __launch_bounds__(256) void gemm_bf16x3(
    const __nv_bfloat16* __restrict__ Ah, const __nv_bfloat16* __restrict__ Al,
    const __nv_bfloat16* __restrict__ Bh, const __nv_bfloat16* __restrict__ Bl,
    float* __restrict__ C, const float* __restrict__ bias,
    int M, int N, int K)
{
    extern __shared__ char smem[];
    const uint32_t sb = smem_u32(smem);
    const int tid = threadIdx.x;
    const int wid = tid >> 5;
    const int wm = wid >> 1;          // 0..3
    const int wn = wid & 1;           // 0..1
    const int m0 = blockIdx.y * 128;
    const int n0 = blockIdx.x * 128;
    const int NK = K / BK;

    // per-thread cp.async mapping: 512 x 16B per matrix, 2 per thread
    // id = it*256 + tid; row = id>>2; seg = id&3
    uint32_t doff[2];
    size_t goffA[2], goffB[2];
    #pragma unroll
    for (int it = 0; it < 2; it++) {
        const int id  = it * 256 + tid;
        const int row = id >> 2;
        const int seg = (id & 3) * 16;     // byte within 64B of row data
        doff[it]  = row * (LDA * 2) + seg;
        goffA[it] = ((size_t)(m0 + row) * K) * 2 + seg;
        goffB[it] = ((size_t)(n0 + row) * K) * 2 + seg;
    }

    auto load_stage = [&](int s, int kc) {
        const uint32_t base = sb + s * STAGE_B;
        const size_t kb = (size_t)kc * (BK * 2);   // byte offset along K
        #pragma unroll
        for (int it = 0; it < 2; it++) {
            cp16(base + 0 * MAT_T + doff[it], (const char*)Ah + goffA[it] + kb);
            cp16(base + 1 * MAT_T + doff[it], (const char*)Al + goffA[it] + kb);
            cp16(base + 2 * MAT_T + doff[it], (const char*)Bh + goffB[it] + kb);
            cp16(base + 3 * MAT_T + doff[it], (const char*)Bl + goffB[it] + kb);
        }
        asm volatile("cp.async.commit_group;" ::: "memory");
    };

    wmma::fragment<wmma::accumulator, 16, 16, 16, float> acc[2][4];
    #pragma unroll
    for (int i = 0; i < 2; i++)
        #pragma unroll
        for (int j = 0; j < 4; j++)
            wmma::fill_fragment(acc[i][j], 0.0f);

    load_stage(0, 0);
    load_stage(1, 1);

    for (int kt = 0; kt < NK; kt++) {
        asm volatile("cp.async.wait_group 1;" ::: "memory");
        __syncthreads();

        const char* stg = smem + (kt & 1) * STAGE_B;
        const __nv_bfloat16* Ash_h = (const __nv_bfloat16*)(stg);
        const __nv_bfloat16* Ash_l = (const __nv_bfloat16*)(stg + MAT_T);
        const __nv_bfloat16* Bsh_h = (const __nv_bfloat16*)(stg + 2 * MAT_T);
        const __nv_bfloat16* Bsh_l = (const __nv_bfloat16*)(stg + 3 * MAT_T);

        #pragma unroll
        for (int ks = 0; ks < BK; ks += 16) {
            wmma::fragment<wmma::matrix_a, 16, 16, 16, __nv_bfloat16, wmma::row_major> ah[2], al[2];
            wmma::fragment<wmma::matrix_b, 16, 16, 16, __nv_bfloat16, wmma::col_major> bh[4], bl[4];
            #pragma unroll
            for (int i = 0; i < 2; i++) {
                const int r = wm * 32 + i * 16;
                wmma::load_matrix_sync(ah[i], Ash_h + r * LDA + ks, LDA);
                wmma::load_matrix_sync(al[i], Ash_l + r * LDA + ks, LDA);
            }
            #pragma unroll
            for (int j = 0; j < 4; j++) {
                const int c = wn * 64 + j * 16;
                wmma::load_matrix_sync(bh[j], Bsh_h + c * LDA + ks, LDA);
                wmma::load_matrix_sync(bl[j], Bsh_l + c * LDA + ks, LDA);
            }
            #pragma unroll
            for (int i = 0; i < 2; i++)
                #pragma unroll
                for (int j = 0; j < 4; j++) {
                    wmma::mma_sync(acc[i][j], ah[i], bh[j], acc[i][j]);
                    wmma::mma_sync(acc[i][j], ah[i], bl[j], acc[i][j]);
                    wmma::mma_sync(acc[i][j], al[i], bh[j], acc[i][j]);
                }
        }

        __syncthreads();
        if (kt + 2 < NK) load_stage(kt & 1, kt + 2);
        else asm volatile("cp.async.commit_group;" ::: "memory");
    }

    // epilogue: frags -> smem (fp32, LDC=132), then bias add + coalesced store
    __syncthreads();
    float* Csh = (float*)smem;
    #pragma unroll
    for (int i = 0; i < 2; i++)
        #pragma unroll
        for (int j = 0; j < 4; j++)
            wmma::store_matrix_sync(
                Csh + (wm * 32 + i * 16) * LDC + wn * 64 + j * 16,
                acc[i][j], LDC, wmma::mem_row_major);
    __syncthreads();

    const int r  = tid >> 1;
    const int c0 = (tid & 1) * 64;
    float* crow = C + (size_t)(m0 + r) * N + n0 + c0;
    const float* srow = Csh + r * LDC + c0;
    #pragma unroll
    for (int j = 0; j < 16; j++) {
        float4 v = *(const float4*)(srow + j * 4);
        if (bias) {
            const float4 bb = *(const float4*)(bias + n0 + c0 + j * 4);
            v.x += bb.x; v.y += bb.y; v.z += bb.z; v.w += bb.w;
        }
        *(float4*)(crow + j * 4) = v;
    }
}

// ---------------------------------------------------------------------------
// Fused attention: one block per (b,h). Thread-per-query-row single pass
// (logits bounded ~|8|, no max subtraction needed in fp32).
// ---------------------------------------------------------------------------
#define ATT_THREADS 224
#define ATT_SMEM    ((2 * NSEQ * HDIM + 729) * (int)sizeof(float))   // 53092 B

__global__ __launch_bounds__(ATT_THREADS) void attention_kernel(
    const float* __restrict__ qkv,   // [12544, 3072]
    const float* __restrict__ rpk,   // [729, 32]
    float* __restrict__ out)         // [12544, 1024]  (B,N,H,HD)
{
    extern __shared__ float smf[];
    float* Ksh = smf;
    float* Vsh = smf + NSEQ * HDIM;
    float* rsh = smf + 2 * NSEQ * HDIM;

    const int h   = blockIdx.x;
    const int b   = blockIdx.y;
    const int tid = threadIdx.x;

    const float* base = qkv + (size_t)b * NSEQ * QKVN + h * HDIM;

    for (int f = tid; f < NSEQ * 8; f += ATT_THREADS) {
        const int j  = f >> 3;
        const int d4 = (f & 7) * 4;
        const size_t row = (size_t)j * QKVN;
        *(float4*)(Ksh + j * HDIM + d4) = *(const float4*)(base + row + CDIM   + d4);
        *(float4*)(Vsh + j * HDIM + d4) = *(const float4*)(base + row + 2*CDIM + d4);
    }
    for (int i = tid; i < 729; i += ATT_THREADS)
        rsh[i] = rpk[(size_t)i * HDIM + h];
    __syncthreads();

    if (tid < NSEQ) {
        const int r = tid;
        const float scale = 0.17677669529663687f;

        float q[HDIM];
        #pragma unroll
        for (int d4 = 0; d4 < 8; d4++) {
            const float4 qv = *(const float4*)(base + (size_t)r * QKVN + d4 * 4);
            q[d4*4+0] = qv.x * scale;
            q[d4*4+1] = qv.y * scale;
            q[d4*4+2] = qv.z * scale;
            q[d4*4+3] = qv.w * scale;
        }

        float acc[HDIM];
        #pragma unroll
        for (int d = 0; d < HDIM; d++) acc[d] = 0.0f;
        float denom = 0.0f;

        const int dyc = (r / 14 + 13) * 27 + (r % 14) + 13;
        int t = 0, xj = 0;

        #pragma unroll 2
        for (int j = 0; j < NSEQ; j++) {
            const float* kj = Ksh + j * HDIM;
            float s0 = 0.f, s1 = 0.f, s2 = 0.f, s3 = 0.f;
            #pragma unroll
            for (int d4 = 0; d4 < 8; d4++) {
                const float4 kv = *(const float4*)(kj + d4 * 4);
                s0 = fmaf(q[d4*4+0], kv.x, s0);
                s1 = fmaf(q[d4*4+1], kv.y, s1);
                s2 = fmaf(q[d4*4+2], kv.z, s2);
                s3 = fmaf(q[d4*4+3], kv.w, s3);
            }
            const float logit = (s0 + s1) + (s2 + s3) + rsh[dyc - t];
            const float p = __expf(logit);
            denom += p;

            const float* vj = Vsh + j * HDIM;
            #pragma unroll
            for (int d4 = 0; d4 < 8; d4++) {
                const float4 vv = *(const float4*)(vj + d4 * 4);
                acc[d4*4+0] = fmaf(p, vv.x, acc[d4*4+0]);
                acc[d4*4+1] = fmaf(p, vv.y, acc[d4*4+1]);
                acc[d4*4+2] = fmaf(p, vv.z, acc[d4*4+2]);
                acc[d4*4+3] = fmaf(p, vv.w, acc[d4*4+3]);
            }
            t++;
            if (++xj == 14) { xj = 0; t += 13; }
        }

        const float inv = 1.0f / denom;
        float* o = out + (size_t)(b * NSEQ + r) * CDIM + h * HDIM;
        #pragma unroll
        for (int d4 = 0; d4 < 8; d4++) {
            float4 v;
            v.x = acc[d4*4+0] * inv;
            v.y = acc[d4*4+1] * inv;
            v.z = acc[d4*4+2] * inv;
            v.w = acc[d4*4+3] * inv;
            *(float4*)(o + d4 * 4) = v;
        }
    }
}

// ---------------------------------------------------------------------------
// Launch
// ---------------------------------------------------------------------------
extern "C" void kernel_launch(void* const* d_in, const int* in_sizes, int n_in,
                              void* d_out, int out_size)
{
    const float* x      = (const float*)d_in[0];
    const float* W_qkv  = (const float*)d_in[1];
    const float* W_proj = (const float*)d_in[2];
    const float* b_proj = (const float*)d_in[3];
    const float* rpk    = (const float*)d_in[4];
    float* out = (float*)d_out;

    float *qkv, *att;
    __nv_bfloat16 *xh, *xl, *wqh, *wql, *wph, *wpl, *ath, *atl;
    cudaGetSymbolAddress((void**)&qkv, g_qkv);
    cudaGetSymbolAddress((void**)&att, g_att);
    cudaGetSymbolAddress((void**)&xh,  g_xh);
    cudaGetSymbolAddress((void**)&xl,  g_xl);
    cudaGetSymbolAddress((void**)&wqh, g_wqh);
    cudaGetSymbolAddress((void**)&wql, g_wql);
    cudaGetSymbolAddress((void**)&wph, g_wph);
    cudaGetSymbolAddress((void**)&wpl, g_wpl);
    cudaGetSymbolAddress((void**)&ath, g_ath);
    cudaGetSymbolAddress((void**)&atl, g_atl);

    cudaFuncSetAttribute(gemm_bf16x3,
                         cudaFuncAttributeMaxDynamicSharedMemorySize, GEMM_SMEM);
    cudaFuncSetAttribute(attention_kernel,
                         cudaFuncAttributeMaxDynamicSharedMemorySize, ATT_SMEM);

    // 0) conversions
    split4_kernel<<<MROWS * CDIM / 1024, 256>>>(x, xh, xl);
    transpose_split_kernel<<<dim3(QKVN / 32, CDIM / 32), dim3(32, 8)>>>(
        W_qkv, wqh, wql, CDIM, QKVN);
    transpose_split_kernel<<<dim3(CDIM / 32, CDIM / 32), dim3(32, 8)>>>(
        W_proj, wph, wpl, CDIM, CDIM);

    // 1) QKV projection: [12544,1024] x [1024,3072]
    gemm_bf16x3<<<dim3(QKVN / 128, MROWS / 128), 256, GEMM_SMEM>>>(
        xh, xl, wqh, wql, qkv, nullptr, MROWS, QKVN, CDIM);

    // 2) fused attention per (b,h)
    attention_kernel<<<dim3(NHEAD, BATCH), ATT_THREADS, ATT_SMEM>>>(qkv, rpk, att);

    // 3) output projection: [12544,1024] x [1024,1024] + bias
    split4_kernel<<<MROWS * CDIM / 1024, 256>>>(att, ath, atl);
    gemm_bf16x3<<<dim3(CDIM / 128, MROWS / 128), 256, GEMM_SMEM>>>(
        ath, atl, wph, wpl, out, b_proj, MROWS, CDIM, CDIM);
}

// round 5
// speedup vs baseline: 2.0315x; 1.2041x over previous
#include <cuda_runtime.h>
#include <cuda_bf16.h>
#include <mma.h>
#include <stdint.h>
#include <math.h>

using namespace nvcuda;

// Problem constants
#define BATCH   64
#define NSEQ    196
#define CDIM    1024
#define NHEAD   32
#define HDIM    32
#define MROWS   12544            // BATCH*NSEQ
#define QKVN    3072             // 3*CDIM

// ---------------------------------------------------------------------------
// Static scratch (no cudaMalloc allowed)
// ---------------------------------------------------------------------------
__device__ float g_qkv[(size_t)MROWS * QKVN];       // [12544, 3072] fp32
__device__ float g_att[(size_t)MROWS * CDIM];       // [12544, 1024] fp32
__device__ __nv_bfloat16 g_xh[(size_t)MROWS * CDIM];
__device__ __nv_bfloat16 g_xl[(size_t)MROWS * CDIM];
__device__ __nv_bfloat16 g_wqh[(size_t)QKVN * CDIM];   // W_qkv^T [3072,1024]
__device__ __nv_bfloat16 g_wql[(size_t)QKVN * CDIM];
__device__ __nv_bfloat16 g_wph[(size_t)CDIM * CDIM];   // W_proj^T [1024,1024]
__device__ __nv_bfloat16 g_wpl[(size_t)CDIM * CDIM];
__device__ __nv_bfloat16 g_ath[(size_t)MROWS * CDIM];
__device__ __nv_bfloat16 g_atl[(size_t)MROWS * CDIM];

// ---------------------------------------------------------------------------
// cp.async helper (baseline PTX, sm_80+)
// ---------------------------------------------------------------------------
__device__ __forceinline__ uint32_t smem_u32(const void* p) {
    uint32_t a;
    asm("{ .reg .u64 t; cvta.to.shared.u64 t, %1; cvt.u32.u64 %0, t; }"
        : "=r"(a) : "l"(p));
    return a;
}
__device__ __forceinline__ void cp16(uint32_t dst, const void* src) {
    asm volatile("cp.async.cg.shared.global [%0], [%1], 16;\n"
                 :: "r"(dst), "l"(src));
}

// ---------------------------------------------------------------------------
// bf16-split conversion kernels
// ---------------------------------------------------------------------------
__global__ __launch_bounds__(256) void split4_kernel(
    const float* __restrict__ in, __nv_bfloat16* __restrict__ hi,
    __nv_bfloat16* __restrict__ lo)
{
    const size_t i0 = ((size_t)blockIdx.x * 256 + threadIdx.x) * 4;
    const float4 v = *(const float4*)(in + i0);
    __nv_bfloat16 h0 = __float2bfloat16(v.x), h1 = __float2bfloat16(v.y);
    __nv_bfloat16 h2 = __float2bfloat16(v.z), h3 = __float2bfloat16(v.w);
    __nv_bfloat16 l0 = __float2bfloat16(v.x - __bfloat162float(h0));
    __nv_bfloat16 l1 = __float2bfloat16(v.y - __bfloat162float(h1));
    __nv_bfloat16 l2 = __float2bfloat16(v.z - __bfloat162float(h2));
    __nv_bfloat16 l3 = __float2bfloat16(v.w - __bfloat162float(h3));
    *(__nv_bfloat162*)(hi + i0)     = __nv_bfloat162(h0, h1);
    *(__nv_bfloat162*)(hi + i0 + 2) = __nv_bfloat162(h2, h3);
    *(__nv_bfloat162*)(lo + i0)     = __nv_bfloat162(l0, l1);
    *(__nv_bfloat162*)(lo + i0 + 2) = __nv_bfloat162(l2, l3);
}

// in: [K, N] fp32 row-major  ->  hi/lo: [N, K] bf16 row-major
__global__ __launch_bounds__(256) void transpose_split_kernel(
    const float* __restrict__ in, __nv_bfloat16* __restrict__ hi,
    __nv_bfloat16* __restrict__ lo, int K, int N)
{
    __shared__ float t[32][33];
    const int bx = blockIdx.x;   // tile over N
    const int by = blockIdx.y;   // tile over K
    const int x = bx * 32 + threadIdx.x;
    #pragma unroll
    for (int i = 0; i < 32; i += 8) {
        const int y = by * 32 + threadIdx.y + i;
        t[threadIdx.y + i][threadIdx.x] = in[(size_t)y * N + x];
    }
    __syncthreads();
    const int k = by * 32 + threadIdx.x;
    #pragma unroll
    for (int i = 0; i < 32; i += 8) {
        const int n = bx * 32 + threadIdx.y + i;
        const float v = t[threadIdx.x][threadIdx.y + i];
        const __nv_bfloat16 h = __float2bfloat16(v);
        hi[(size_t)n * K + k] = h;
        lo[(size_t)n * K + k] = __float2bfloat16(v - __bfloat162float(h));
    }
}

// ---------------------------------------------------------------------------
// HMMA bf16-split GEMM: C[M,N] = A*B^T (+bias).
// A=[M,K] hi/lo bf16 row-major, B=[N,K] hi/lo bf16 row-major.
// 128x128 CTA tile, BK=32, 4 warps (2x2), warp tile 64x64,
// wmma 16x16x16 bf16->fp32, cp.async double buffer, bias epilogue via smem.
// 128 threads/CTA -> 2 CTAs/SM (80KB smem each).
// ---------------------------------------------------------------------------
#define BK       32
#define LDA      40                           // padded bf16 leading dim (80 B)
#define MAT_T    (128 * LDA * 2)              // 10240 B per matrix tile
#define STAGE_B  (4 * MAT_T)                  // 40960 B (Ah, Al, Bh, Bl)
#define GEMM_SMEM (2 * STAGE_B)               // 81920 B (>= epilogue 67584 B)
#define LDC      132                          // fp32 epilogue leading dim

__global__ __launch_bounds__(128) void gemm_bf16x3(
    const __nv_bfloat16* __restrict__ Ah, const __nv_bfloat16* __restrict__ Al,
    const __nv_bfloat16* __restrict__ Bh, const __nv_bfloat16* __restrict__ Bl,
    float* __restrict__ C, const float* __restrict__ bias,
    int M, int N, int K)
{
    extern __shared__ char smem[];
    const uint32_t sb = smem_u32(smem);
    const int tid = threadIdx.x;
    const int wid = tid >> 5;
    const int lane = tid & 31;
    const int wm = wid >> 1;          // 0..1 (64-row slab)
    const int wn = wid & 1;           // 0..1 (64-col slab)
    const int m0 = blockIdx.y * 128;
    const int n0 = blockIdx.x * 128;
    const int NK = K / BK;

    // per-thread cp.async mapping: 512 x 16B per matrix, 4 per thread
    uint32_t doff[4];
    size_t goffA[4], goffB[4];
    #pragma unroll
    for (int it = 0; it < 4; it++) {
        const int id  = it * 128 + tid;
        const int row = id >> 2;
        const int seg = (id & 3) * 16;     // byte within 64B of row data
        doff[it]  = row * (LDA * 2) + seg;
        goffA[it] = ((size_t)(m0 + row) * K) * 2 + seg;
        goffB[it] = ((size_t)(n0 + row) * K) * 2 + seg;
    }

    auto load_stage = [&](int s, int kc) {
        const uint32_t base = sb + s * STAGE_B;
        const size_t kb = (size_t)kc * (BK * 2);   // byte offset along K
        #pragma unroll
        for (int it = 0; it < 4; it++) {
            cp16(base + 0 * MAT_T + doff[it], (const char*)Ah + goffA[it] + kb);
            cp16(base + 1 * MAT_T + doff[it], (const char*)Al + goffA[it] + kb);
            cp16(base + 2 * MAT_T + doff[it], (const char*)Bh + goffB[it] + kb);
            cp16(base + 3 * MAT_T + doff[it], (const char*)Bl + goffB[it] + kb);
        }
        asm volatile("cp.async.commit_group;" ::: "memory");
    };

    wmma::fragment<wmma::accumulator, 16, 16, 16, float> acc[4][4];
    #pragma unroll
    for (int i = 0; i < 4; i++)
        #pragma unroll
        for (int j = 0; j < 4; j++)
            wmma::fill_fragment(acc[i][j], 0.0f);

    load_stage(0, 0);
    load_stage(1, 1);

    for (int kt = 0; kt < NK; kt++) {
        asm volatile("cp.async.wait_group 1;" ::: "memory");
        __syncthreads();

        const char* stg = smem + (kt & 1) * STAGE_B;
        const __nv_bfloat16* Ash_h = (const __nv_bfloat16*)(stg);
        const __nv_bfloat16* Ash_l = (const __nv_bfloat16*)(stg + MAT_T);
        const __nv_bfloat16* Bsh_h = (const __nv_bfloat16*)(stg + 2 * MAT_T);
        const __nv_bfloat16* Bsh_l = (const __nv_bfloat16*)(stg + 3 * MAT_T);

        #pragma unroll
        for (int ks = 0; ks < BK; ks += 16) {
            wmma::fragment<wmma::matrix_a, 16, 16, 16, __nv_bfloat16, wmma::row_major> ah[4], al[4];
            #pragma unroll
            for (int i = 0; i < 4; i++) {
                const int r = wm * 64 + i * 16;
                wmma::load_matrix_sync(ah[i], Ash_h + r * LDA + ks, LDA);
                wmma::load_matrix_sync(al[i], Ash_l + r * LDA + ks, LDA);
            }
            #pragma unroll
            for (int j = 0; j < 4; j++) {
                wmma::fragment<wmma::matrix_b, 16, 16, 16, __nv_bfloat16, wmma::col_major> bh, bl;
                const int c = wn * 64 + j * 16;
                wmma::load_matrix_sync(bh, Bsh_h + c * LDA + ks, LDA);
                wmma::load_matrix_sync(bl, Bsh_l + c * LDA + ks, LDA);
                #pragma unroll
                for (int i = 0; i < 4; i++) {
                    wmma::mma_sync(acc[i][j], ah[i], bh, acc[i][j]);
                    wmma::mma_sync(acc[i][j], ah[i], bl, acc[i][j]);
                    wmma::mma_sync(acc[i][j], al[i], bh, acc[i][j]);
                }
            }
        }

        __syncthreads();
        if (kt + 2 < NK) load_stage(kt & 1, kt + 2);
        else asm volatile("cp.async.commit_group;" ::: "memory");
    }

    // epilogue: frags -> smem (fp32, LDC=132), then bias add + coalesced store
    __syncthreads();
    float* Csh = (float*)smem;
    #pragma unroll
    for (int i = 0; i < 4; i++)
        #pragma unroll
        for (int j = 0; j < 4; j++)
            wmma::store_matrix_sync(
                Csh + (wm * 64 + i * 16) * LDC + wn * 64 + j * 16,
                acc[i][j], LDC, wmma::mem_row_major);
    __syncthreads();

    // warp w covers rows [32w, 32w+32); lane covers 4 cols -> 512B/row store
    float4 bb = make_float4(0.f, 0.f, 0.f, 0.f);
    if (bias) bb = *(const float4*)(bias + n0 + lane * 4);
    #pragma unroll 4
    for (int i = 0; i < 32; i++) {
        const int r = wid * 32 + i;
        float4 v = *(const float4*)(Csh + r * LDC + lane * 4);
        v.x += bb.x; v.y += bb.y; v.z += bb.z; v.w += bb.w;
        *(float4*)(C + (size_t)(m0 + r) * N + n0 + lane * 4) = v;
    }
}

// ---------------------------------------------------------------------------
// Fused attention: one block per (b,h). Thread-per-query-row single pass
// (logits bounded ~|8|, no max subtraction needed in fp32).
// ---------------------------------------------------------------------------
#define ATT_THREADS 224
#define ATT_SMEM    ((2 * NSEQ * HDIM + 729) * (int)sizeof(float))   // 53092 B

__global__ __launch_bounds__(ATT_THREADS) void attention_kernel(
    const float* __restrict__ qkv,   // [12544, 3072]
    const float* __restrict__ rpk,   // [729, 32]
    float* __restrict__ out)         // [12544, 1024]  (B,N,H,HD)
{
    extern __shared__ float smf[];
    float* Ksh = smf;
    float* Vsh = smf + NSEQ * HDIM;
    float* rsh = smf + 2 * NSEQ * HDIM;

    const int h   = blockIdx.x;
    const int b   = blockIdx.y;
    const int tid = threadIdx.x;

    const float* base = qkv + (size_t)b * NSEQ * QKVN + h * HDIM;

    for (int f = tid; f < NSEQ * 8; f += ATT_THREADS) {
        const int j  = f >> 3;
        const int d4 = (f & 7) * 4;
        const size_t row = (size_t)j * QKVN;
        *(float4*)(Ksh + j * HDIM + d4) = *(const float4*)(base + row + CDIM   + d4);
        *(float4*)(Vsh + j * HDIM + d4) = *(const float4*)(base + row + 2*CDIM + d4);
    }
    for (int i = tid; i < 729; i += ATT_THREADS)
        rsh[i] = rpk[(size_t)i * HDIM + h];
    __syncthreads();

    if (tid < NSEQ) {
        const int r = tid;
        const float scale = 0.17677669529663687f;

        float q[HDIM];
        #pragma unroll
        for (int d4 = 0; d4 < 8; d4++) {
            const float4 qv = *(const float4*)(base + (size_t)r * QKVN + d4 * 4);
            q[d4*4+0] = qv.x * scale;
            q[d4*4+1] = qv.y * scale;
            q[d4*4+2] = qv.z * scale;
            q[d4*4+3] = qv.w * scale;
        }

        float acc[HDIM];
        #pragma unroll
        for (int d = 0; d < HDIM; d++) acc[d] = 0.0f;
        float denom = 0.0f;

        const int dyc = (r / 14 + 13) * 27 + (r % 14) + 13;
        int t = 0, xj = 0;

        #pragma unroll 2
        for (int j = 0; j < NSEQ; j++) {
            const float* kj = Ksh + j * HDIM;
            float s0 = 0.f, s1 = 0.f, s2 = 0.f, s3 = 0.f;
            #pragma unroll
            for (int d4 = 0; d4 < 8; d4++) {
                const float4 kv = *(const float4*)(kj + d4 * 4);
                s0 = fmaf(q[d4*4+0], kv.x, s0);
                s1 = fmaf(q[d4*4+1], kv.y, s1);
                s2 = fmaf(q[d4*4+2], kv.z, s2);
                s3 = fmaf(q[d4*4+3], kv.w, s3);
            }
            const float logit = (s0 + s1) + (s2 + s3) + rsh[dyc - t];
            const float p = __expf(logit);
            denom += p;

            const float* vj = Vsh + j * HDIM;
            #pragma unroll
            for (int d4 = 0; d4 < 8; d4++) {
                const float4 vv = *(const float4*)(vj + d4 * 4);
                acc[d4*4+0] = fmaf(p, vv.x, acc[d4*4+0]);
                acc[d4*4+1] = fmaf(p, vv.y, acc[d4*4+1]);
                acc[d4*4+2] = fmaf(p, vv.z, acc[d4*4+2]);
                acc[d4*4+3] = fmaf(p, vv.w, acc[d4*4+3]);
            }
            t++;
            if (++xj == 14) { xj = 0; t += 13; }
        }

        const float inv = 1.0f / denom;
        float* o = out + (size_t)(b * NSEQ + r) * CDIM + h * HDIM;
        #pragma unroll
        for (int d4 = 0; d4 < 8; d4++) {
            float4 v;
            v.x = acc[d4*4+0] * inv;
            v.y = acc[d4*4+1] * inv;
            v.z = acc[d4*4+2] * inv;
            v.w = acc[d4*4+3] * inv;
            *(float4*)(o + d4 * 4) = v;
        }
    }
}

// ---------------------------------------------------------------------------
// Launch
// ---------------------------------------------------------------------------
extern "C" void kernel_launch(void* const* d_in, const int* in_sizes, int n_in,
                              void* d_out, int out_size)
{
    const float* x      = (const float*)d_in[0];
    const float* W_qkv  = (const float*)d_in[1];
    const float* W_proj = (const float*)d_in[2];
    const float* b_proj = (const float*)d_in[3];
    const float* rpk    = (const float*)d_in[4];
    float* out = (float*)d_out;

    float *qkv, *att;
    __nv_bfloat16 *xh, *xl, *wqh, *wql, *wph, *wpl, *ath, *atl;
    cudaGetSymbolAddress((void**)&qkv, g_qkv);
    cudaGetSymbolAddress((void**)&att, g_att);
    cudaGetSymbolAddress((void**)&xh,  g_xh);
    cudaGetSymbolAddress((void**)&xl,  g_xl);
    cudaGetSymbolAddress((void**)&wqh, g_wqh);
    cudaGetSymbolAddress((void**)&wql, g_wql);
    cudaGetSymbolAddress((void**)&wph, g_wph);
    cudaGetSymbolAddress((void**)&wpl, g_wpl);
    cudaGetSymbolAddress((void**)&ath, g_ath);
    cudaGetSymbolAddress((void**)&atl, g_atl);

    cudaFuncSetAttribute(gemm_bf16x3,
                         cudaFuncAttributeMaxDynamicSharedMemorySize, GEMM_SMEM);
    cudaFuncSetAttribute(attention_kernel,
                         cudaFuncAttributeMaxDynamicSharedMemorySize, ATT_SMEM);

    // 0) conversions
    split4_kernel<<<MROWS * CDIM / 1024, 256>>>(x, xh, xl);
    transpose_split_kernel<<<dim3(QKVN / 32, CDIM / 32), dim3(32, 8)>>>(
        W_qkv, wqh, wql, CDIM, QKVN);
    transpose_split_kernel<<<dim3(CDIM / 32, CDIM / 32), dim3(32, 8)>>>(
        W_proj, wph, wpl, CDIM, CDIM);

    // 1) QKV projection: [12544,1024] x [1024,3072]
    gemm_bf16x3<<<dim3(QKVN / 128, MROWS / 128), 128, GEMM_SMEM>>>(
        xh, xl, wqh, wql, qkv, nullptr, MROWS, QKVN, CDIM);

    // 2) fused attention per (b,h)
    attention_kernel<<<dim3(NHEAD, BATCH), ATT_THREADS, ATT_SMEM>>>(qkv, rpk, att);

    // 3) output projection: [12544,1024] x [1024,1024] + bias
    split4_kernel<<<MROWS * CDIM / 1024, 256>>>(att, ath, atl);
    gemm_bf16x3<<<dim3(CDIM / 128, MROWS / 128), 128, GEMM_SMEM>>>(
        ath, atl, wph, wpl, out, b_proj, MROWS, CDIM, CDIM);
}